// round 11
// baseline (speedup 1.0000x reference)
#include <cuda_runtime.h>
#include <cuda_bf16.h>
#include <cstdint>

#define NN 100000
#define NE 300000
#define MT 10000

typedef unsigned long long u64;
typedef unsigned int u32;
typedef __nv_bfloat16 bf16;

// ---------------- scratch (device globals; no allocation allowed) ----------------
__device__ float g_node_h [(size_t)NN*256];
__device__ float g_base   [(size_t)NE*256];
__device__ float g_y      [(size_t)NE*256];
__device__ float g_aggA   [(size_t)NN*256];
__device__ float g_aggB   [(size_t)NN*256];
__device__ float g_nodesum[(size_t)NN*256];
__device__ bf16 g_fn_h[(size_t)NN*256], g_fn_l[(size_t)NN*256];
__device__ bf16 g_fe_h[(size_t)NE*64],  g_fe_l[(size_t)NE*64];
__device__ bf16 g_tm_h[(size_t)MT*256], g_tm_l[(size_t)MT*256];
__device__ bf16 g_ns_h[(size_t)NN*256], g_ns_l[(size_t)NN*256];
__device__ bf16 g_B1h[256*256], g_B1l[256*256];
__device__ bf16 g_B2h[256*64],  g_B2l[256*64];
__device__ bf16 g_B3h[256*256], g_B3l[256*256];
__device__ bf16 g_B4h[256*256], g_B4l[256*256];
__device__ bf16 g_B5h[256*256], g_B5l[256*256];

// ---------------- helpers ----------------
__device__ __forceinline__ u32 smem_u32(const void* p) {
    u32 a; asm("{ .reg .u64 t; cvta.to.shared.u64 t, %1; cvt.u32.u64 %0, t; }" : "=r"(a) : "l"(p));
    return a;
}
__device__ __forceinline__ void cp16(u32 dst, const void* src) {
    asm volatile("cp.async.cg.shared.global [%0], [%1], 16;" :: "r"(dst), "l"(src));
}
__device__ __forceinline__ void red2(float* p, float a, float b) {
    asm volatile("red.global.add.v2.f32 [%0], {%1,%2};" :: "l"(p), "f"(a), "f"(b) : "memory");
}
__device__ __forceinline__ void red4(float* p, float a, float b, float c, float d) {
    asm volatile("red.global.add.v4.f32 [%0], {%1,%2,%3,%4};"
                 :: "l"(p), "f"(a), "f"(b), "f"(c), "f"(d) : "memory");
}
__device__ __forceinline__ void ldsm4(u32* r, u32 addr) {
    asm volatile("ldmatrix.sync.aligned.m8n8.x4.shared.b16 {%0,%1,%2,%3}, [%4];"
                 : "=r"(r[0]), "=r"(r[1]), "=r"(r[2]), "=r"(r[3]) : "r"(addr));
}
__device__ __forceinline__ void mma16816(float* d, const u32* a, const u32* b) {
    asm volatile("mma.sync.aligned.m16n8k16.row.col.f32.bf16.bf16.f32 "
                 "{%0,%1,%2,%3}, {%4,%5,%6,%7}, {%8,%9}, {%0,%1,%2,%3};"
                 : "+f"(d[0]), "+f"(d[1]), "+f"(d[2]), "+f"(d[3])
                 : "r"(a[0]), "r"(a[1]), "r"(a[2]), "r"(a[3]), "r"(b[0]), "r"(b[1]));
}
__device__ __forceinline__ u32 pack_hi2(float x, float y) {
    __nv_bfloat162 h; h.x = __float2bfloat16(x); h.y = __float2bfloat16(y);
    return *(u32*)&h;
}
__device__ __forceinline__ u32 pack_lo2(float x, float y, u32 hibits) {
    __nv_bfloat162 h = *(__nv_bfloat162*)&hibits;
    __nv_bfloat162 l;
    l.x = __float2bfloat16(x - __bfloat162float(h.x));
    l.y = __float2bfloat16(y - __bfloat162float(h.y));
    return *(u32*)&l;
}
__device__ __forceinline__ void split_store4(bf16* hp, bf16* lp, float4 v) {
    u32 h0 = pack_hi2(v.x, v.y), h1 = pack_hi2(v.z, v.w);
    ((u32*)hp)[0] = h0; ((u32*)hp)[1] = h1;
    ((u32*)lp)[0] = pack_lo2(v.x, v.y, h0); ((u32*)lp)[1] = pack_lo2(v.z, v.w, h1);
}

#define BUF_BYTES 10240u
#define STAGE_BYTES (4u * BUF_BYTES)
#define SM_BYTES (2 * STAGE_BYTES)       // 81920

// ------------------- mma.sync GEMM: C[M,256] = A[M,K] @ W[K,256] -------------------
// MODE 0: C = acc
// MODE 1: C = acc + addmat[gidx[r]] + bias
// MODE 2: C[gidx[r]] += acc
// MODE 6: C = relu(A@B + A2@B2 + bias)   (fused readout; 16 chunks)
template<int MODE>
__global__ __launch_bounds__(256, 2)
void tgemm(const bf16* __restrict__ Ah, const bf16* __restrict__ Al,
           const bf16* __restrict__ Bh, const bf16* __restrict__ Bl,
           const bf16* __restrict__ Ah2, const bf16* __restrict__ Al2,
           const bf16* __restrict__ Bh2, const bf16* __restrict__ Bl2,
           float* __restrict__ C, int M, int K,
           const float* __restrict__ bias, const float* __restrict__ addmat,
           const int* __restrict__ gidx)
{
    extern __shared__ char smem[];
    const u32 sb = smem_u32(smem);
    const int tid  = threadIdx.x;
    const int lane = tid & 31, w = tid >> 5;
    const int wm = w >> 2, wn = w & 3;
    const int bm = blockIdx.y * 128;
    const int bn = blockIdx.x * 128;
    const int nchunks = (MODE == 6) ? 16 : (K >> 5);

    float acc[4][4][4];
    #pragma unroll
    for (int i = 0; i < 4; i++)
        #pragma unroll
        for (int j = 0; j < 4; j++)
            #pragma unroll
            for (int q = 0; q < 4; q++) acc[i][j][q] = 0.f;

    const int lr = tid >> 1;
    const int ch = (tid & 1) * 2;
    int growA = bm + lr; if (growA >= M) growA = M - 1;
    const u32 so = (u32)lr * 80u + (u32)ch * 16u;

    auto load_chunk = [&](int c, int s) {
        const bf16 *pAh = Ah, *pAl = Al, *pBh = Bh, *pBl = Bl;
        int cc = c;
        if (MODE == 6 && c >= 8) { pAh = Ah2; pAl = Al2; pBh = Bh2; pBl = Bl2; cc = c - 8; }
        const u32 base = sb + (u32)s * STAGE_BYTES;
        const size_t gbA = ((size_t)growA * K + cc * 32 + ch * 8) * 2;
        const size_t gbB = ((size_t)(bn + lr) * K + cc * 32 + ch * 8) * 2;
        cp16(base + so,                  (const char*)pAh + gbA);
        cp16(base + so + 16,             (const char*)pAh + gbA + 16);
        cp16(base + BUF_BYTES + so,      (const char*)pAl + gbA);
        cp16(base + BUF_BYTES + so + 16, (const char*)pAl + gbA + 16);
        cp16(base + 2*BUF_BYTES + so,      (const char*)pBh + gbB);
        cp16(base + 2*BUF_BYTES + so + 16, (const char*)pBh + gbB + 16);
        cp16(base + 3*BUF_BYTES + so,      (const char*)pBl + gbB);
        cp16(base + 3*BUF_BYTES + so + 16, (const char*)pBl + gbB + 16);
    };

    const u32 aAddr = (u32)(wm * 64 + (lane & 15)) * 80u + (u32)(lane >> 4) * 16u;
    const u32 bAddr = (u32)(wn * 32 + ((lane >> 4) << 3) + (lane & 7)) * 80u
                    + (u32)((lane >> 3) & 1) * 16u;

    load_chunk(0, 0);
    asm volatile("cp.async.commit_group;" ::: "memory");

    for (int c = 0; c < nchunks; c++) {
        const int s = c & 1;
        if (c + 1 < nchunks) {
            load_chunk(c + 1, (c + 1) & 1);
            asm volatile("cp.async.commit_group;" ::: "memory");
            asm volatile("cp.async.wait_group 1;" ::: "memory");
        } else {
            asm volatile("cp.async.wait_group 0;" ::: "memory");
        }
        __syncthreads();

        const u32 stage = sb + (u32)s * STAGE_BYTES;
        #pragma unroll
        for (int t = 0; t < 3; t++) {
            const u32 sA = stage + ((t < 2) ? 0u : BUF_BYTES) + aAddr;
            const u32 sB = stage + ((t == 1) ? 3u : 2u) * BUF_BYTES + bAddr;
            #pragma unroll
            for (int ks = 0; ks < 2; ks++) {
                u32 af[4][4], bfv[2][4];
                #pragma unroll
                for (int mt = 0; mt < 4; mt++)
                    ldsm4(af[mt], sA + (u32)mt * (16u * 80u) + (u32)ks * 32u);
                #pragma unroll
                for (int p = 0; p < 2; p++)
                    ldsm4(bfv[p], sB + (u32)p * (16u * 80u) + (u32)ks * 32u);
                #pragma unroll
                for (int mt = 0; mt < 4; mt++)
                    #pragma unroll
                    for (int nt = 0; nt < 4; nt++)
                        mma16816(acc[mt][nt], af[mt], &bfv[nt >> 1][(nt & 1) * 2]);
            }
        }
        __syncthreads();
    }

    #pragma unroll
    for (int mt = 0; mt < 4; mt++) {
        #pragma unroll
        for (int half = 0; half < 2; half++) {
            const int r = bm + wm * 64 + mt * 16 + (lane >> 2) + half * 8;
            if (r >= M) continue;
            int g = 0;
            if (MODE == 1 || MODE == 2) g = __ldg(gidx + r);
            const size_t rowC = (size_t)r * 256;
            #pragma unroll
            for (int nt = 0; nt < 4; nt++) {
                const int c0 = bn + wn * 32 + nt * 8 + (lane & 3) * 2;
                float vx = acc[mt][nt][2 * half], vy = acc[mt][nt][2 * half + 1];
                if constexpr (MODE == 0) {
                    *(float2*)(C + rowC + c0) = make_float2(vx, vy);
                } else if constexpr (MODE == 1) {
                    const float2 ad = *(const float2*)(addmat + (size_t)g * 256 + c0);
                    const float2 bi = *(const float2*)(bias + c0);
                    *(float2*)(C + rowC + c0) = make_float2(vx + ad.x + bi.x, vy + ad.y + bi.y);
                } else if constexpr (MODE == 2) {
                    const size_t rowG = (size_t)g * 256;
                    float2 bs = *(float2*)(C + rowG + c0);
                    *(float2*)(C + rowG + c0) = make_float2(bs.x + vx, bs.y + vy);
                } else if constexpr (MODE == 6) {
                    const float2 bi = *(const float2*)(bias + c0);
                    *(float2*)(C + rowC + c0) =
                        make_float2(fmaxf(vx + bi.x, 0.f), fmaxf(vy + bi.y, 0.f));
                }
            }
        }
    }
}

// --------- fused E-GEMM: A computed on the fly, y = A @ W3, red agg[edst] += y ---------
// FM 1: A = relu(base[e])                              (iter 1)
// FM 2: A = relu(base[e] + agg[esrc[e]] - y[e^1])      (iter 2; y overwritten in-place,
//        safe: e^1 lies in the same 128-row tile, each CTA touches only its own rows)
template<int FM>
__global__ __launch_bounds__(256)
void tgemm_fused(const float* __restrict__ Abase, const float* __restrict__ agg,
                 float* __restrict__ y,
                 const bf16* __restrict__ Bh, const bf16* __restrict__ Bl,
                 const int* __restrict__ esrc, const int* __restrict__ edst,
                 float* __restrict__ aggout, int M)
{
    extern __shared__ char smem[];
    const u32 sb = smem_u32(smem);
    const int tid  = threadIdx.x;
    const int lane = tid & 31, wi = tid >> 5;
    const int wm = wi >> 2, wn = wi & 3;
    const int bm = blockIdx.y * 128;
    const int bn = blockIdx.x * 128;

    float acc[4][4][4];
    #pragma unroll
    for (int i = 0; i < 4; i++)
        #pragma unroll
        for (int j = 0; j < 4; j++)
            #pragma unroll
            for (int q = 0; q < 4; q++) acc[i][j][q] = 0.f;

    const int r    = tid >> 1;           // A/B row handled by this thread
    const int half = tid & 1;            // 16-col half
    int e = bm + r; if (e >= M) e = M - 1;
    const int srow = (FM == 2) ? __ldg(esrc + e) : 0;
    const int erev = e ^ 1;
    const u32 so = (u32)r * 80u + (u32)half * 32u;

    float4 vb[4], va[4], vy[4];
    auto ldA = [&](int c) {
        const size_t co = (size_t)c * 32 + half * 16;
        const float4* bp = (const float4*)(Abase + (size_t)e * 256 + co);
        #pragma unroll
        for (int i = 0; i < 4; i++) vb[i] = __ldg(bp + i);
        if (FM == 2) {
            const float4* ap = (const float4*)(agg + (size_t)srow * 256 + co);
            const float4* yp = (const float4*)(y   + (size_t)erev * 256 + co);
            #pragma unroll
            for (int i = 0; i < 4; i++) { va[i] = __ldg(ap + i); vy[i] = __ldg(yp + i); }
        }
    };
    auto stA = [&](int s) {
        u32 hv[8], lv[8];
        #pragma unroll
        for (int i = 0; i < 4; i++) {
            float4 m;
            if (FM == 2) {
                m.x = fmaxf(vb[i].x + va[i].x - vy[i].x, 0.f);
                m.y = fmaxf(vb[i].y + va[i].y - vy[i].y, 0.f);
                m.z = fmaxf(vb[i].z + va[i].z - vy[i].z, 0.f);
                m.w = fmaxf(vb[i].w + va[i].w - vy[i].w, 0.f);
            } else {
                m.x = fmaxf(vb[i].x, 0.f); m.y = fmaxf(vb[i].y, 0.f);
                m.z = fmaxf(vb[i].z, 0.f); m.w = fmaxf(vb[i].w, 0.f);
            }
            hv[2*i]   = pack_hi2(m.x, m.y);
            hv[2*i+1] = pack_hi2(m.z, m.w);
            lv[2*i]   = pack_lo2(m.x, m.y, hv[2*i]);
            lv[2*i+1] = pack_lo2(m.z, m.w, hv[2*i+1]);
        }
        char* base = smem + (size_t)s * STAGE_BYTES + so;
        ((uint4*)base)[0] = make_uint4(hv[0], hv[1], hv[2], hv[3]);
        ((uint4*)base)[1] = make_uint4(hv[4], hv[5], hv[6], hv[7]);
        char* lbase = base + BUF_BYTES;
        ((uint4*)lbase)[0] = make_uint4(lv[0], lv[1], lv[2], lv[3]);
        ((uint4*)lbase)[1] = make_uint4(lv[4], lv[5], lv[6], lv[7]);
    };
    auto ldB = [&](int c, int s) {
        const u32 b0 = sb + (u32)s * STAGE_BYTES + 2u * BUF_BYTES;
        const size_t gb = ((size_t)(bn + r) * 256 + c * 32 + half * 16) * 2;
        cp16(b0 + so,                  (const char*)Bh + gb);
        cp16(b0 + so + 16,             (const char*)Bh + gb + 16);
        cp16(b0 + BUF_BYTES + so,      (const char*)Bl + gb);
        cp16(b0 + BUF_BYTES + so + 16, (const char*)Bl + gb + 16);
    };

    const u32 aAddr = (u32)(wm * 64 + (lane & 15)) * 80u + (u32)(lane >> 4) * 16u;
    const u32 bAddr = (u32)(wn * 32 + ((lane >> 4) << 3) + (lane & 7)) * 80u
                    + (u32)((lane >> 3) & 1) * 16u;

    // prologue: stage 0 fully built
    ldA(0); stA(0);
    ldB(0, 0);
    asm volatile("cp.async.commit_group;" ::: "memory");

    for (int c = 0; c < 8; c++) {
        const int s = c & 1;
        if (c + 1 < 8) {
            ldA(c + 1);                               // LDGs issue; consumed after MMA
            ldB(c + 1, (c + 1) & 1);
            asm volatile("cp.async.commit_group;" ::: "memory");
            asm volatile("cp.async.wait_group 1;" ::: "memory");
        } else {
            asm volatile("cp.async.wait_group 0;" ::: "memory");
        }
        __syncthreads();

        const u32 stage = sb + (u32)s * STAGE_BYTES;
        #pragma unroll
        for (int t = 0; t < 3; t++) {
            const u32 sA = stage + ((t < 2) ? 0u : BUF_BYTES) + aAddr;
            const u32 sB = stage + ((t == 1) ? 3u : 2u) * BUF_BYTES + bAddr;
            #pragma unroll
            for (int ks = 0; ks < 2; ks++) {
                u32 af[4][4], bfv[2][4];
                #pragma unroll
                for (int mt = 0; mt < 4; mt++)
                    ldsm4(af[mt], sA + (u32)mt * (16u * 80u) + (u32)ks * 32u);
                #pragma unroll
                for (int p = 0; p < 2; p++)
                    ldsm4(bfv[p], sB + (u32)p * (16u * 80u) + (u32)ks * 32u);
                #pragma unroll
                for (int mt = 0; mt < 4; mt++)
                    #pragma unroll
                    for (int nt = 0; nt < 4; nt++)
                        mma16816(acc[mt][nt], af[mt], &bfv[nt >> 1][(nt & 1) * 2]);
            }
        }
        if (c + 1 < 8) stA((c + 1) & 1);              // after MMA(c): latency hidden
        __syncthreads();
    }

    // epilogue: y[row] = acc ; red aggout[edst[row]] += acc
    #pragma unroll
    for (int mt = 0; mt < 4; mt++) {
        #pragma unroll
        for (int half2 = 0; half2 < 2; half2++) {
            const int rr = bm + wm * 64 + mt * 16 + (lane >> 2) + half2 * 8;
            if (rr >= M) continue;
            const int g = __ldg(edst + rr);
            const size_t rowC = (size_t)rr * 256;
            #pragma unroll
            for (int nt = 0; nt < 4; nt++) {
                const int c0 = bn + wn * 32 + nt * 8 + (lane & 3) * 2;
                float vx = acc[mt][nt][2 * half2], vy2 = acc[mt][nt][2 * half2 + 1];
                *(float2*)(y + rowC + c0) = make_float2(vx, vy2);
                red2(aggout + (size_t)g * 256 + c0, vx, vy2);
            }
        }
    }
}

// ---------------- fused prologue: zeros + input splits + weight transposes ----------------
#define PR_Z  (3 * NN * 64)
#define PR_FN (NN * 64)
#define PR_FE (NE * 16)
#define PR_TM (MT * 64)
#define PR_BULK (PR_Z + PR_FN + PR_FE + PR_TM)
#define PR_W  (65536 * 4 + 16384)
#define PR_TOTAL (PR_BULK + PR_W)

__global__ __launch_bounds__(256)
void prologue_k(const float* __restrict__ f_node, const float* __restrict__ f_edge,
                const float* __restrict__ tree_msg,
                const float* __restrict__ W1, const float* __restrict__ W2,
                const float* __restrict__ W3, const float* __restrict__ W4,
                const float* __restrict__ W5)
{
    int i = blockIdx.x * blockDim.x + threadIdx.x;
    if (i >= PR_TOTAL) return;
    if (i < PR_Z) {
        int j = i;
        float4* p;
        if (j < NN * 64) p = (float4*)g_aggA;
        else if (j < 2 * NN * 64) { p = (float4*)g_aggB; j -= NN * 64; }
        else { p = (float4*)g_nodesum; j -= 2 * NN * 64; }
        p[j] = make_float4(0.f, 0.f, 0.f, 0.f);
        return;
    }
    i -= PR_Z;
    if (i < PR_FN) {
        float4 v = ((const float4*)f_node)[i];
        split_store4(g_fn_h + (size_t)i * 4, g_fn_l + (size_t)i * 4, v);
        return;
    }
    i -= PR_FN;
    if (i < PR_FE) {
        float4 v = ((const float4*)f_edge)[i];
        split_store4(g_fe_h + (size_t)i * 4, g_fe_l + (size_t)i * 4, v);
        return;
    }
    i -= PR_FE;
    if (i < PR_TM) {
        float4 v = ((const float4*)tree_msg)[i];
        split_store4(g_tm_h + (size_t)i * 4, g_tm_l + (size_t)i * 4, v);
        return;
    }
    i -= PR_TM;
    const float* W; bf16 *h, *l; int K;
    if (i < 65536)                { W = W1; h = g_B1h; l = g_B1l; K = 256; }
    else if (i < 65536 + 16384)   { i -= 65536; W = W2; h = g_B2h; l = g_B2l; K = 64; }
    else if (i < 2*65536 + 16384) { i -= 65536 + 16384; W = W3; h = g_B3h; l = g_B3l; K = 256; }
    else if (i < 3*65536 + 16384) { i -= 2*65536 + 16384; W = W4; h = g_B4h; l = g_B4l; K = 256; }
    else                          { i -= 3*65536 + 16384; W = W5; h = g_B5h; l = g_B5l; K = 256; }
    int n = i / K, k = i % K;
    float v = W[(size_t)k * 256 + n];
    bf16 hi = __float2bfloat16(v);
    h[i] = hi;
    l[i] = __float2bfloat16(v - __bfloat162float(hi));
}

// ---------------- final combine: red nodesum[dst] += relu(base + agg[src] - y[e^1]) ------
__global__ __launch_bounds__(256)
void combine_final_k(const float* __restrict__ base, const float* __restrict__ agg,
                     const float* __restrict__ y, const int* __restrict__ esrc,
                     const int* __restrict__ edst, float* __restrict__ nodesum)
{
    int gid = blockIdx.x * blockDim.x + threadIdx.x;
    if (gid >= NE * 32) return;
    int e = gid >> 5;
    int c = (gid & 31) << 3;
    int s = __ldg(esrc + e);
    const float* bp = base + (size_t)e * 256 + c;
    const float* ap = agg  + (size_t)s * 256 + c;
    const float* yp = y    + (size_t)(e ^ 1) * 256 + c;
    float4 b0 = ((const float4*)bp)[0], b1 = ((const float4*)bp)[1];
    float4 a0 = ((const float4*)ap)[0], a1 = ((const float4*)ap)[1];
    float4 y0 = ((const float4*)yp)[0], y1 = ((const float4*)yp)[1];
    int d = __ldg(edst + e);
    float* np = nodesum + (size_t)d * 256 + c;
    red4(np, fmaxf(b0.x + a0.x - y0.x, 0.f), fmaxf(b0.y + a0.y - y0.y, 0.f),
             fmaxf(b0.z + a0.z - y0.z, 0.f), fmaxf(b0.w + a0.w - y0.w, 0.f));
    red4(np + 4, fmaxf(b1.x + a1.x - y1.x, 0.f), fmaxf(b1.y + a1.y - y1.y, 0.f),
                 fmaxf(b1.z + a1.z - y1.z, 0.f), fmaxf(b1.w + a1.w - y1.w, 0.f));
}

// split nodesum -> bf16 hi/lo, 8 elems/thread
__global__ void split_k(const float* __restrict__ x, bf16* __restrict__ h,
                        bf16* __restrict__ l, int n8)
{
    int i = blockIdx.x * blockDim.x + threadIdx.x;
    if (i >= n8) return;
    const float4* xp = (const float4*)(x + (size_t)i * 8);
    float4 v0 = xp[0], v1 = xp[1];
    uint4 hv, lv;
    hv.x = pack_hi2(v0.x, v0.y); hv.y = pack_hi2(v0.z, v0.w);
    hv.z = pack_hi2(v1.x, v1.y); hv.w = pack_hi2(v1.z, v1.w);
    lv.x = pack_lo2(v0.x, v0.y, hv.x); lv.y = pack_lo2(v0.z, v0.w, hv.y);
    lv.z = pack_lo2(v1.x, v1.y, hv.z); lv.w = pack_lo2(v1.z, v1.w, hv.w);
    *(uint4*)(h + (size_t)i * 8) = hv;
    *(uint4*)(l + (size_t)i * 8) = lv;
}

// --------------------------------- launch ---------------------------------
extern "C" void kernel_launch(void* const* d_in, const int* in_sizes, int n_in,
                              void* d_out, int out_size)
{
    const float* f_node   = (const float*)d_in[0];
    const float* f_edge   = (const float*)d_in[1];
    const float* tree_msg = (const float*)d_in[2];
    const float* W1       = (const float*)d_in[3];
    const float* W2       = (const float*)d_in[4];
    const float* W3       = (const float*)d_in[5];
    const float* b1       = (const float*)d_in[6];
    const float* W4       = (const float*)d_in[7];
    const float* W5       = (const float*)d_in[8];
    const float* b2       = (const float*)d_in[9];
    const int* edge_src   = (const int*)d_in[10];
    const int* edge_dst   = (const int*)d_in[11];
    const int* tree_tgt   = (const int*)d_in[12];
    float* out = (float*)d_out;

    float *node_h, *base, *y, *aggA, *aggB, *nodesum;
    bf16 *fnh, *fnl, *feh, *fel, *tmh, *tml, *nsh, *nsl;
    bf16 *B1h, *B1l, *B2h, *B2l, *B3h, *B3l, *B4h, *B4l, *B5h, *B5l;
    cudaGetSymbolAddress((void**)&node_h,  g_node_h);
    cudaGetSymbolAddress((void**)&base,    g_base);
    cudaGetSymbolAddress((void**)&y,       g_y);
    cudaGetSymbolAddress((void**)&aggA,    g_aggA);
    cudaGetSymbolAddress((void**)&aggB,    g_aggB);
    cudaGetSymbolAddress((void**)&nodesum, g_nodesum);
    cudaGetSymbolAddress((void**)&fnh, g_fn_h); cudaGetSymbolAddress((void**)&fnl, g_fn_l);
    cudaGetSymbolAddress((void**)&feh, g_fe_h); cudaGetSymbolAddress((void**)&fel, g_fe_l);
    cudaGetSymbolAddress((void**)&tmh, g_tm_h); cudaGetSymbolAddress((void**)&tml, g_tm_l);
    cudaGetSymbolAddress((void**)&nsh, g_ns_h); cudaGetSymbolAddress((void**)&nsl, g_ns_l);
    cudaGetSymbolAddress((void**)&B1h, g_B1h);  cudaGetSymbolAddress((void**)&B1l, g_B1l);
    cudaGetSymbolAddress((void**)&B2h, g_B2h);  cudaGetSymbolAddress((void**)&B2l, g_B2l);
    cudaGetSymbolAddress((void**)&B3h, g_B3h);  cudaGetSymbolAddress((void**)&B3l, g_B3l);
    cudaGetSymbolAddress((void**)&B4h, g_B4h);  cudaGetSymbolAddress((void**)&B4l, g_B4l);
    cudaGetSymbolAddress((void**)&B5h, g_B5h);  cudaGetSymbolAddress((void**)&B5l, g_B5l);

    cudaFuncSetAttribute(tgemm<0>, cudaFuncAttributeMaxDynamicSharedMemorySize, SM_BYTES);
    cudaFuncSetAttribute(tgemm<1>, cudaFuncAttributeMaxDynamicSharedMemorySize, SM_BYTES);
    cudaFuncSetAttribute(tgemm<2>, cudaFuncAttributeMaxDynamicSharedMemorySize, SM_BYTES);
    cudaFuncSetAttribute(tgemm<6>, cudaFuncAttributeMaxDynamicSharedMemorySize, SM_BYTES);
    cudaFuncSetAttribute(tgemm_fused<1>, cudaFuncAttributeMaxDynamicSharedMemorySize, SM_BYTES);
    cudaFuncSetAttribute(tgemm_fused<2>, cudaFuncAttributeMaxDynamicSharedMemorySize, SM_BYTES);

    const dim3 blk(256);
    const int combGrid = (NE * 32 + 255) / 256;
    const dim3 gN(2, (NN + 127) / 128);
    const dim3 gE(2, (NE + 127) / 128);
    const dim3 gT(2, (MT + 127) / 128);

    // 1) fused prologue
    prologue_k<<<(PR_TOTAL + 255) / 256, blk>>>(f_node, f_edge, tree_msg, W1, W2, W3, W4, W5);

    // 2) node_h = f_node @ W1
    tgemm<0><<<gN, blk, SM_BYTES>>>(fnh, fnl, B1h, B1l, nullptr, nullptr, nullptr, nullptr,
                                    node_h, NN, 256, nullptr, nullptr, nullptr);
    // 3) base = f_edge @ W2 + node_h[src] + b1
    tgemm<1><<<gE, blk, SM_BYTES>>>(feh, fel, B2h, B2l, nullptr, nullptr, nullptr, nullptr,
                                    base, NE, 64, b1, node_h, edge_src);
    // 4) base[tree_tgt] += tree_msg @ W3
    tgemm<2><<<gT, blk, SM_BYTES>>>(tmh, tml, B3h, B3l, nullptr, nullptr, nullptr, nullptr,
                                    base, MT, 256, nullptr, nullptr, tree_tgt);

    // 5) iter 1 (fused): y1 = relu(base) @ W3 ; aggA = segsum(y1, dst)
    tgemm_fused<1><<<gE, blk, SM_BYTES>>>(base, nullptr, y, B3h, B3l,
                                          edge_src, edge_dst, aggA, NE);
    // 6) iter 2 (fused): y2 = relu(base + aggA[src] - y1[rev]) @ W3 ; aggB = segsum(y2, dst)
    tgemm_fused<2><<<gE, blk, SM_BYTES>>>(base, aggA, y, B3h, B3l,
                                          edge_src, edge_dst, aggB, NE);
    // 7) iter 3 fused with readout reduce
    combine_final_k<<<combGrid, blk>>>(base, aggB, y, edge_src, edge_dst, nodesum);

    // 8) split nodesum; 9) fused readout
    split_k<<<(NN * 32 + 255) / 256, blk>>>(nodesum, nsh, nsl, NN * 32);
    tgemm<6><<<gN, blk, SM_BYTES>>>(fnh, fnl, B4h, B4l, nsh, nsl, B5h, B5l,
                                    out, NN, 256, b2, nullptr, nullptr);
}

// round 12
// speedup vs baseline: 1.2911x; 1.2911x over previous
#include <cuda_runtime.h>
#include <cuda_fp16.h>
#include <cstdint>

#define NN 100000
#define NE 300000
#define MT 10000

typedef unsigned long long u64;
typedef unsigned int u32;

// ---------------- scratch (device globals; no allocation allowed) ----------------
__device__ float g_node_h [(size_t)NN*256];
__device__ float g_base   [(size_t)NE*256];
__device__ float g_y      [(size_t)NE*256];
__device__ float g_aggA   [(size_t)NN*256];
__device__ float g_aggB   [(size_t)NN*256];
__device__ float g_nodesum[(size_t)NN*256];
// fp16 hi/lo split buffers (A-side)
__device__ __half g_fn_h[(size_t)NN*256], g_fn_l[(size_t)NN*256];
__device__ __half g_fe_h[(size_t)NE*64],  g_fe_l[(size_t)NE*64];
__device__ __half g_tm_h[(size_t)MT*256], g_tm_l[(size_t)MT*256];
__device__ __half g_a_h [(size_t)NE*256], g_a_l [(size_t)NE*256];
__device__ __half g_ns_h[(size_t)NN*256], g_ns_l[(size_t)NN*256];
// B matrices transposed, single fp16: B[n][k] = W[k][n]
__device__ __half g_B1[256*256];
__device__ __half g_B2[256*64];
__device__ __half g_B3[256*256];
__device__ __half g_B4[256*256];
__device__ __half g_B5[256*256];

// ---------------- helpers ----------------
__device__ __forceinline__ u32 smem_u32(const void* p) {
    u32 a; asm("{ .reg .u64 t; cvta.to.shared.u64 t, %1; cvt.u32.u64 %0, t; }" : "=r"(a) : "l"(p));
    return a;
}
__device__ __forceinline__ void cp16(u32 dst, const void* src) {
    asm volatile("cp.async.cg.shared.global [%0], [%1], 16;" :: "r"(dst), "l"(src));
}
__device__ __forceinline__ void red2(float* p, float a, float b) {
    asm volatile("red.global.add.v2.f32 [%0], {%1,%2};" :: "l"(p), "f"(a), "f"(b) : "memory");
}
__device__ __forceinline__ void red4(float* p, float a, float b, float c, float d) {
    asm volatile("red.global.add.v4.f32 [%0], {%1,%2,%3,%4};"
                 :: "l"(p), "f"(a), "f"(b), "f"(c), "f"(d) : "memory");
}
__device__ __forceinline__ void ldsm4(u32* r, u32 addr) {
    asm volatile("ldmatrix.sync.aligned.m8n8.x4.shared.b16 {%0,%1,%2,%3}, [%4];"
                 : "=r"(r[0]), "=r"(r[1]), "=r"(r[2]), "=r"(r[3]) : "r"(addr));
}
__device__ __forceinline__ void mma16816(float* d, const u32* a, const u32* b) {
    asm volatile("mma.sync.aligned.m16n8k16.row.col.f32.f16.f16.f32 "
                 "{%0,%1,%2,%3}, {%4,%5,%6,%7}, {%8,%9}, {%0,%1,%2,%3};"
                 : "+f"(d[0]), "+f"(d[1]), "+f"(d[2]), "+f"(d[3])
                 : "r"(a[0]), "r"(a[1]), "r"(a[2]), "r"(a[3]), "r"(b[0]), "r"(b[1]));
}
__device__ __forceinline__ u32 pack_hi2(float x, float y) {
    __half2 h = __floats2half2_rn(x, y);
    return *(u32*)&h;
}
__device__ __forceinline__ u32 pack_lo2(float x, float y, u32 hibits) {
    __half2 h = *(__half2*)&hibits;
    __half2 l = __floats2half2_rn(x - __half2float(__low2half(h)),
                                  y - __half2float(__high2half(h)));
    return *(u32*)&l;
}
__device__ __forceinline__ void split_store2(__half* hp, __half* lp, float x, float y) {
    u32 hb = pack_hi2(x, y);
    *(u32*)hp = hb;
    *(u32*)lp = pack_lo2(x, y, hb);
}
__device__ __forceinline__ void split_store4(__half* hp, __half* lp, float4 v) {
    u32 h0 = pack_hi2(v.x, v.y), h1 = pack_hi2(v.z, v.w);
    ((u32*)hp)[0] = h0; ((u32*)hp)[1] = h1;
    ((u32*)lp)[0] = pack_lo2(v.x, v.y, h0); ((u32*)lp)[1] = pack_lo2(v.z, v.w, h1);
}

// smem: 2 stages x [AH | AL | B], each buffer 128 rows x 80 bytes = 10240 B
#define BUF_BYTES 10240u
#define STAGE_BYTES (3u * BUF_BYTES)
#define SM_BYTES (2 * STAGE_BYTES)       // 61440 -> 2 CTAs/SM easily

// ------------------- mma.sync GEMM: C[M,256] = A[M,K] @ W[K,256] -------------------
// fp16 2-term: Ah@B + Al@B, fp32 accumulate. CTA tile 128x128, grid (2, tiles_m).
// MODE 0: C = acc
// MODE 1: C = acc + addmat[gidx[r]] + bias; also write relu-split to rh/rl
// MODE 2: C[gidx[r]] += acc; re-write relu-split of that row
// MODE 3: C = acc; red agg[gidx[r]] += acc
// MODE 6: C = relu(A@B + A2@B2 + bias)   (fused readout; 16 chunks)
template<int MODE>
__global__ __launch_bounds__(256, 2)
void tgemm(const __half* __restrict__ Ah, const __half* __restrict__ Al,
           const __half* __restrict__ B,
           const __half* __restrict__ Ah2, const __half* __restrict__ Al2,
           const __half* __restrict__ B2,
           float* __restrict__ C, int M, int K,
           const float* __restrict__ bias, const float* __restrict__ addmat,
           const int* __restrict__ gidx, float* __restrict__ agg,
           __half* __restrict__ rh, __half* __restrict__ rl)
{
    extern __shared__ char smem[];
    const u32 sb = smem_u32(smem);
    const int tid  = threadIdx.x;
    const int lane = tid & 31, w = tid >> 5;
    const int wm = w >> 2, wn = w & 3;          // 2 x 4 warp grid; warp tile 64x32
    const int bm = blockIdx.y * 128;
    const int bn = blockIdx.x * 128;
    const int nchunks = (MODE == 6) ? 16 : (K >> 5);

    float acc[4][4][4];
    #pragma unroll
    for (int i = 0; i < 4; i++)
        #pragma unroll
        for (int j = 0; j < 4; j++)
            #pragma unroll
            for (int q = 0; q < 4; q++) acc[i][j][q] = 0.f;

    const int lr = tid >> 1;
    const int ch = (tid & 1) * 2;
    int growA = bm + lr; if (growA >= M) growA = M - 1;
    const u32 so = (u32)lr * 80u + (u32)ch * 16u;

    auto load_chunk = [&](int c, int s) {
        const __half *pAh = Ah, *pAl = Al, *pB = B;
        int cc = c;
        if (MODE == 6 && c >= 8) { pAh = Ah2; pAl = Al2; pB = B2; cc = c - 8; }
        const u32 base = sb + (u32)s * STAGE_BYTES;
        const size_t gbA = ((size_t)growA * K + cc * 32 + ch * 8) * 2;
        const size_t gbB = ((size_t)(bn + lr) * K + cc * 32 + ch * 8) * 2;
        cp16(base + so,                  (const char*)pAh + gbA);
        cp16(base + so + 16,             (const char*)pAh + gbA + 16);
        cp16(base + BUF_BYTES + so,      (const char*)pAl + gbA);
        cp16(base + BUF_BYTES + so + 16, (const char*)pAl + gbA + 16);
        cp16(base + 2*BUF_BYTES + so,      (const char*)pB + gbB);
        cp16(base + 2*BUF_BYTES + so + 16, (const char*)pB + gbB + 16);
    };

    const u32 aAddr = (u32)(wm * 64 + (lane & 15)) * 80u + (u32)(lane >> 4) * 16u;
    const u32 bAddr = (u32)(wn * 32 + ((lane >> 4) << 3) + (lane & 7)) * 80u
                    + (u32)((lane >> 3) & 1) * 16u;

    load_chunk(0, 0);
    asm volatile("cp.async.commit_group;" ::: "memory");

    for (int c = 0; c < nchunks; c++) {
        const int s = c & 1;
        if (c + 1 < nchunks) {
            load_chunk(c + 1, (c + 1) & 1);
            asm volatile("cp.async.commit_group;" ::: "memory");
            asm volatile("cp.async.wait_group 1;" ::: "memory");
        } else {
            asm volatile("cp.async.wait_group 0;" ::: "memory");
        }
        __syncthreads();

        const u32 stage = sb + (u32)s * STAGE_BYTES;
        #pragma unroll
        for (int ks = 0; ks < 2; ks++) {
            // B fragments loaded once, reused by both A-terms
            u32 bfv[2][4];
            #pragma unroll
            for (int p = 0; p < 2; p++)
                ldsm4(bfv[p], stage + 2u*BUF_BYTES + bAddr + (u32)p * (16u * 80u) + (u32)ks * 32u);
            #pragma unroll
            for (int t = 0; t < 2; t++) {
                const u32 sA = stage + (u32)t * BUF_BYTES + aAddr + (u32)ks * 32u;
                u32 af[4][4];
                #pragma unroll
                for (int mt = 0; mt < 4; mt++)
                    ldsm4(af[mt], sA + (u32)mt * (16u * 80u));
                #pragma unroll
                for (int mt = 0; mt < 4; mt++)
                    #pragma unroll
                    for (int nt = 0; nt < 4; nt++)
                        mma16816(acc[mt][nt], af[mt], &bfv[nt >> 1][(nt & 1) * 2]);
            }
        }
        __syncthreads();
    }

    // ---------------- epilogue ----------------
    #pragma unroll
    for (int mt = 0; mt < 4; mt++) {
        #pragma unroll
        for (int half = 0; half < 2; half++) {
            const int r = bm + wm * 64 + mt * 16 + (lane >> 2) + half * 8;
            if (r >= M) continue;
            int g = 0;
            if (MODE == 1 || MODE == 2 || MODE == 3) g = __ldg(gidx + r);
            const size_t rowC = (size_t)r * 256;
            #pragma unroll
            for (int nt = 0; nt < 4; nt++) {
                const int c0 = bn + wn * 32 + nt * 8 + (lane & 3) * 2;
                float vx = acc[mt][nt][2 * half], vy = acc[mt][nt][2 * half + 1];
                if constexpr (MODE == 0) {
                    *(float2*)(C + rowC + c0) = make_float2(vx, vy);
                } else if constexpr (MODE == 1) {
                    const float2 ad = *(const float2*)(addmat + (size_t)g * 256 + c0);
                    const float2 bi = *(const float2*)(bias + c0);
                    vx += ad.x + bi.x; vy += ad.y + bi.y;
                    *(float2*)(C + rowC + c0) = make_float2(vx, vy);
                    split_store2(rh + rowC + c0, rl + rowC + c0,
                                 fmaxf(vx, 0.f), fmaxf(vy, 0.f));
                } else if constexpr (MODE == 2) {
                    const size_t rowG = (size_t)g * 256;
                    float2 bs = *(float2*)(C + rowG + c0);
                    bs.x += vx; bs.y += vy;
                    *(float2*)(C + rowG + c0) = bs;
                    split_store2(rh + rowG + c0, rl + rowG + c0,
                                 fmaxf(bs.x, 0.f), fmaxf(bs.y, 0.f));
                } else if constexpr (MODE == 3) {
                    *(float2*)(C + rowC + c0) = make_float2(vx, vy);
                    red2(agg + (size_t)g * 256 + c0, vx, vy);
                } else if constexpr (MODE == 6) {
                    const float2 bi = *(const float2*)(bias + c0);
                    *(float2*)(C + rowC + c0) =
                        make_float2(fmaxf(vx + bi.x, 0.f), fmaxf(vy + bi.y, 0.f));
                }
            }
        }
    }
}

// ---------------- fused prologue: zeros + input splits + weight transposes ----------------
#define PR_Z  (3 * NN * 64)
#define PR_FN (NN * 64)
#define PR_FE (NE * 16)
#define PR_TM (MT * 64)
#define PR_BULK (PR_Z + PR_FN + PR_FE + PR_TM)
#define PR_W  (65536 * 4 + 16384)
#define PR_TOTAL (PR_BULK + PR_W)

__global__ __launch_bounds__(256)
void prologue_k(const float* __restrict__ f_node, const float* __restrict__ f_edge,
                const float* __restrict__ tree_msg,
                const float* __restrict__ W1, const float* __restrict__ W2,
                const float* __restrict__ W3, const float* __restrict__ W4,
                const float* __restrict__ W5)
{
    int i = blockIdx.x * blockDim.x + threadIdx.x;
    if (i >= PR_TOTAL) return;
    if (i < PR_Z) {
        int j = i;
        float4* p;
        if (j < NN * 64) p = (float4*)g_aggA;
        else if (j < 2 * NN * 64) { p = (float4*)g_aggB; j -= NN * 64; }
        else { p = (float4*)g_nodesum; j -= 2 * NN * 64; }
        p[j] = make_float4(0.f, 0.f, 0.f, 0.f);
        return;
    }
    i -= PR_Z;
    if (i < PR_FN) {
        float4 v = ((const float4*)f_node)[i];
        split_store4(g_fn_h + (size_t)i * 4, g_fn_l + (size_t)i * 4, v);
        return;
    }
    i -= PR_FN;
    if (i < PR_FE) {
        float4 v = ((const float4*)f_edge)[i];
        split_store4(g_fe_h + (size_t)i * 4, g_fe_l + (size_t)i * 4, v);
        return;
    }
    i -= PR_FE;
    if (i < PR_TM) {
        float4 v = ((const float4*)tree_msg)[i];
        split_store4(g_tm_h + (size_t)i * 4, g_tm_l + (size_t)i * 4, v);
        return;
    }
    i -= PR_TM;
    const float* W; __half* h; int K;
    if (i < 65536)                { W = W1; h = g_B1; K = 256; }
    else if (i < 65536 + 16384)   { i -= 65536; W = W2; h = g_B2; K = 64; }
    else if (i < 2*65536 + 16384) { i -= 65536 + 16384; W = W3; h = g_B3; K = 256; }
    else if (i < 3*65536 + 16384) { i -= 2*65536 + 16384; W = W4; h = g_B4; K = 256; }
    else                          { i -= 3*65536 + 16384; W = W5; h = g_B5; K = 256; }
    int n = i / K, k = i % K;
    h[i] = __float2half_rn(W[(size_t)k * 256 + n]);
}

// ---------------- combine: m = relu(base + agg[src] - y[e^1]), 8 floats/thread --------
template<bool FINAL>
__global__ __launch_bounds__(256)
void combine_k(const float* __restrict__ base, const float* __restrict__ agg,
               const float* __restrict__ y, const int* __restrict__ esrc,
               const int* __restrict__ edst,
               __half* __restrict__ mh, __half* __restrict__ ml, float* __restrict__ nodesum)
{
    int gid = blockIdx.x * blockDim.x + threadIdx.x;
    if (gid >= NE * 32) return;
    int e = gid >> 5;
    int c = (gid & 31) << 3;
    int s = __ldg(esrc + e);
    const float* bp = base + (size_t)e * 256 + c;
    const float* ap = agg  + (size_t)s * 256 + c;
    const float* yp = y    + (size_t)(e ^ 1) * 256 + c;
    float4 b0 = ((const float4*)bp)[0], b1 = ((const float4*)bp)[1];
    float4 a0 = ((const float4*)ap)[0], a1 = ((const float4*)ap)[1];
    float4 y0 = ((const float4*)yp)[0], y1 = ((const float4*)yp)[1];
    float m0 = fmaxf(b0.x + a0.x - y0.x, 0.f);
    float m1 = fmaxf(b0.y + a0.y - y0.y, 0.f);
    float m2 = fmaxf(b0.z + a0.z - y0.z, 0.f);
    float m3 = fmaxf(b0.w + a0.w - y0.w, 0.f);
    float m4 = fmaxf(b1.x + a1.x - y1.x, 0.f);
    float m5 = fmaxf(b1.y + a1.y - y1.y, 0.f);
    float m6 = fmaxf(b1.z + a1.z - y1.z, 0.f);
    float m7 = fmaxf(b1.w + a1.w - y1.w, 0.f);
    if (FINAL) {
        int d = __ldg(edst + e);
        float* np = nodesum + (size_t)d * 256 + c;
        red4(np,     m0, m1, m2, m3);
        red4(np + 4, m4, m5, m6, m7);
    } else {
        uint4 hv, lv;
        hv.x = pack_hi2(m0, m1); hv.y = pack_hi2(m2, m3);
        hv.z = pack_hi2(m4, m5); hv.w = pack_hi2(m6, m7);
        lv.x = pack_lo2(m0, m1, hv.x); lv.y = pack_lo2(m2, m3, hv.y);
        lv.z = pack_lo2(m4, m5, hv.z); lv.w = pack_lo2(m6, m7, hv.w);
        *(uint4*)(mh + (size_t)e * 256 + c) = hv;
        *(uint4*)(ml + (size_t)e * 256 + c) = lv;
    }
}

// split nodesum -> fp16 hi/lo, 8 elems/thread, 16B stores
__global__ void split_k(const float* __restrict__ x, __half* __restrict__ h,
                        __half* __restrict__ l, int n8)
{
    int i = blockIdx.x * blockDim.x + threadIdx.x;
    if (i >= n8) return;
    const float4* xp = (const float4*)(x + (size_t)i * 8);
    float4 v0 = xp[0], v1 = xp[1];
    uint4 hv, lv;
    hv.x = pack_hi2(v0.x, v0.y); hv.y = pack_hi2(v0.z, v0.w);
    hv.z = pack_hi2(v1.x, v1.y); hv.w = pack_hi2(v1.z, v1.w);
    lv.x = pack_lo2(v0.x, v0.y, hv.x); lv.y = pack_lo2(v0.z, v0.w, hv.y);
    lv.z = pack_lo2(v1.x, v1.y, hv.z); lv.w = pack_lo2(v1.z, v1.w, hv.w);
    *(uint4*)(h + (size_t)i * 8) = hv;
    *(uint4*)(l + (size_t)i * 8) = lv;
}

// --------------------------------- launch ---------------------------------
extern "C" void kernel_launch(void* const* d_in, const int* in_sizes, int n_in,
                              void* d_out, int out_size)
{
    const float* f_node   = (const float*)d_in[0];
    const float* f_edge   = (const float*)d_in[1];
    const float* tree_msg = (const float*)d_in[2];
    const float* W1       = (const float*)d_in[3];
    const float* W2       = (const float*)d_in[4];
    const float* W3       = (const float*)d_in[5];
    const float* b1       = (const float*)d_in[6];
    const float* W4       = (const float*)d_in[7];
    const float* W5       = (const float*)d_in[8];
    const float* b2       = (const float*)d_in[9];
    const int* edge_src   = (const int*)d_in[10];
    const int* edge_dst   = (const int*)d_in[11];
    const int* tree_tgt   = (const int*)d_in[12];
    float* out = (float*)d_out;

    float *node_h, *base, *y, *aggA, *aggB, *nodesum;
    __half *fnh, *fnl, *feh, *fel, *tmh, *tml, *ah, *al, *nsh, *nsl;
    __half *B1, *B2, *B3, *B4, *B5;
    cudaGetSymbolAddress((void**)&node_h,  g_node_h);
    cudaGetSymbolAddress((void**)&base,    g_base);
    cudaGetSymbolAddress((void**)&y,       g_y);
    cudaGetSymbolAddress((void**)&aggA,    g_aggA);
    cudaGetSymbolAddress((void**)&aggB,    g_aggB);
    cudaGetSymbolAddress((void**)&nodesum, g_nodesum);
    cudaGetSymbolAddress((void**)&fnh, g_fn_h); cudaGetSymbolAddress((void**)&fnl, g_fn_l);
    cudaGetSymbolAddress((void**)&feh, g_fe_h); cudaGetSymbolAddress((void**)&fel, g_fe_l);
    cudaGetSymbolAddress((void**)&tmh, g_tm_h); cudaGetSymbolAddress((void**)&tml, g_tm_l);
    cudaGetSymbolAddress((void**)&ah,  g_a_h);  cudaGetSymbolAddress((void**)&al,  g_a_l);
    cudaGetSymbolAddress((void**)&nsh, g_ns_h); cudaGetSymbolAddress((void**)&nsl, g_ns_l);
    cudaGetSymbolAddress((void**)&B1, g_B1);
    cudaGetSymbolAddress((void**)&B2, g_B2);
    cudaGetSymbolAddress((void**)&B3, g_B3);
    cudaGetSymbolAddress((void**)&B4, g_B4);
    cudaGetSymbolAddress((void**)&B5, g_B5);

    cudaFuncSetAttribute(tgemm<0>, cudaFuncAttributeMaxDynamicSharedMemorySize, SM_BYTES);
    cudaFuncSetAttribute(tgemm<1>, cudaFuncAttributeMaxDynamicSharedMemorySize, SM_BYTES);
    cudaFuncSetAttribute(tgemm<2>, cudaFuncAttributeMaxDynamicSharedMemorySize, SM_BYTES);
    cudaFuncSetAttribute(tgemm<3>, cudaFuncAttributeMaxDynamicSharedMemorySize, SM_BYTES);
    cudaFuncSetAttribute(tgemm<6>, cudaFuncAttributeMaxDynamicSharedMemorySize, SM_BYTES);

    const dim3 blk(256);
    const int combGrid = (NE * 32 + 255) / 256;
    const dim3 gN(2, (NN + 127) / 128);
    const dim3 gE(2, (NE + 127) / 128);
    const dim3 gT(2, (MT + 127) / 128);

    // ---- fused prologue: zeros + input splits + weight transposes ----
    prologue_k<<<(PR_TOTAL + 255) / 256, blk>>>(f_node, f_edge, tree_msg, W1, W2, W3, W4, W5);

    // ---- node_h = f_node @ W1 ----
    tgemm<0><<<gN, blk, SM_BYTES>>>(fnh, fnl, B1, nullptr, nullptr, nullptr,
                                    node_h, NN, 256, nullptr, nullptr, nullptr, nullptr, nullptr, nullptr);
    // ---- base = f_edge @ W2 + node_h[src] + b1 ; write relu-split(ah/al) ----
    tgemm<1><<<gE, blk, SM_BYTES>>>(feh, fel, B2, nullptr, nullptr, nullptr,
                                    base, NE, 64, b1, node_h, edge_src, nullptr, ah, al);
    // ---- base[tree_tgt] += tree_msg @ W3 ; patch relu-split rows ----
    tgemm<2><<<gT, blk, SM_BYTES>>>(tmh, tml, B3, nullptr, nullptr, nullptr,
                                    base, MT, 256, nullptr, nullptr, tree_tgt, nullptr, ah, al);

    // ---- iter 1: y1 = relu(base) @ W3 ; aggA = segsum(y1, dst) ----
    tgemm<3><<<gE, blk, SM_BYTES>>>(ah, al, B3, nullptr, nullptr, nullptr,
                                    y, NE, 256, nullptr, nullptr, edge_dst, aggA, nullptr, nullptr);
    combine_k<false><<<combGrid, blk>>>(base, aggA, y, edge_src, edge_dst, ah, al, nullptr);

    // ---- iter 2: y2 = msg2 @ W3 ; aggB = segsum(y2, dst) ----
    tgemm<3><<<gE, blk, SM_BYTES>>>(ah, al, B3, nullptr, nullptr, nullptr,
                                    y, NE, 256, nullptr, nullptr, edge_dst, aggB, nullptr, nullptr);
    // ---- iter 3 fused with readout reduce ----
    combine_k<true><<<combGrid, blk>>>(base, aggB, y, edge_src, edge_dst, nullptr, nullptr, nodesum);

    // ---- fused readout: out = relu(f_node @ W4 + node_sum @ W5 + b2) ----
    split_k<<<(NN * 32 + 255) / 256, blk>>>(nodesum, nsh, nsl, NN * 32);
    tgemm<6><<<gN, blk, SM_BYTES>>>(fnh, fnl, B4, nsh, nsl, B5,
                                    out, NN, 256, b2, nullptr, nullptr, nullptr, nullptr, nullptr);
}

// round 13
// speedup vs baseline: 1.6142x; 1.2502x over previous
#include <cuda_runtime.h>
#include <cuda_fp16.h>
#include <cstdint>

#define NN 100000
#define NE 300000
#define MT 10000

typedef unsigned long long u64;
typedef unsigned int u32;

// ---------------- scratch (device globals; no allocation allowed) ----------------
__device__ float g_node_h [(size_t)NN*256];
__device__ float g_base   [(size_t)NE*256];
__device__ float g_y      [(size_t)NE*256];
__device__ float g_aggA   [(size_t)NN*256];
__device__ float g_aggB   [(size_t)NN*256];
__device__ float g_nodesum[(size_t)NN*256];
// single-fp16 A-side buffers
__device__ __half g_fn[(size_t)NN*256];
__device__ __half g_fe[(size_t)NE*64];
__device__ __half g_tm[(size_t)MT*256];
__device__ __half g_a [(size_t)NE*256];
__device__ __half g_ns[(size_t)NN*256];
// B matrices transposed, single fp16: B[n][k] = W[k][n]
__device__ __half g_B1[256*256];
__device__ __half g_B2[256*64];
__device__ __half g_B3[256*256];
__device__ __half g_B4[256*256];
__device__ __half g_B5[256*256];

// ---------------- helpers ----------------
__device__ __forceinline__ u32 smem_u32(const void* p) {
    u32 a; asm("{ .reg .u64 t; cvta.to.shared.u64 t, %1; cvt.u32.u64 %0, t; }" : "=r"(a) : "l"(p));
    return a;
}
__device__ __forceinline__ void cp16(u32 dst, const void* src) {
    asm volatile("cp.async.cg.shared.global [%0], [%1], 16;" :: "r"(dst), "l"(src));
}
__device__ __forceinline__ void red2(float* p, float a, float b) {
    asm volatile("red.global.add.v2.f32 [%0], {%1,%2};" :: "l"(p), "f"(a), "f"(b) : "memory");
}
__device__ __forceinline__ void red4(float* p, float a, float b, float c, float d) {
    asm volatile("red.global.add.v4.f32 [%0], {%1,%2,%3,%4};"
                 :: "l"(p), "f"(a), "f"(b), "f"(c), "f"(d) : "memory");
}
__device__ __forceinline__ void ldsm4(u32* r, u32 addr) {
    asm volatile("ldmatrix.sync.aligned.m8n8.x4.shared.b16 {%0,%1,%2,%3}, [%4];"
                 : "=r"(r[0]), "=r"(r[1]), "=r"(r[2]), "=r"(r[3]) : "r"(addr));
}
__device__ __forceinline__ void mma16816(float* d, const u32* a, const u32* b) {
    asm volatile("mma.sync.aligned.m16n8k16.row.col.f32.f16.f16.f32 "
                 "{%0,%1,%2,%3}, {%4,%5,%6,%7}, {%8,%9}, {%0,%1,%2,%3};"
                 : "+f"(d[0]), "+f"(d[1]), "+f"(d[2]), "+f"(d[3])
                 : "r"(a[0]), "r"(a[1]), "r"(a[2]), "r"(a[3]), "r"(b[0]), "r"(b[1]));
}
__device__ __forceinline__ u32 pack2(float x, float y) {
    __half2 h = __floats2half2_rn(x, y);
    return *(u32*)&h;
}
__device__ __forceinline__ void conv_store4(__half* hp, float4 v) {
    ((u32*)hp)[0] = pack2(v.x, v.y);
    ((u32*)hp)[1] = pack2(v.z, v.w);
}

// smem: 2 stages x [A | B], each buffer 128 rows x 80 bytes = 10240 B
#define BUF_BYTES 10240u
#define STAGE_BYTES (2u * BUF_BYTES)
#define SM_BYTES (2 * STAGE_BYTES)       // 40960

// ------------------- mma.sync GEMM: C[M,256] = A[M,K] @ W[K,256] -------------------
// single fp16 term, fp32 accumulate. CTA tile 128x128, grid (2, tiles_m).
// MODE 0: C = acc
// MODE 1: C = acc + addmat[gidx[r]] + bias; also write relu fp16 -> rout
// MODE 2: C[gidx[r]] += acc; re-write relu fp16 of that row
// MODE 3: C = acc; red agg[gidx[r]] += acc
// MODE 6: C = relu(A@B + A2@B2 + bias)   (fused readout; 16 chunks)
template<int MODE>
__global__ __launch_bounds__(256, 2)
void tgemm(const __half* __restrict__ A, const __half* __restrict__ B,
           const __half* __restrict__ A2, const __half* __restrict__ B2,
           float* __restrict__ C, int M, int K,
           const float* __restrict__ bias, const float* __restrict__ addmat,
           const int* __restrict__ gidx, float* __restrict__ agg,
           __half* __restrict__ rout)
{
    extern __shared__ char smem[];
    const u32 sb = smem_u32(smem);
    const int tid  = threadIdx.x;
    const int lane = tid & 31, w = tid >> 5;
    const int wm = w >> 2, wn = w & 3;          // 2 x 4 warp grid; warp tile 64x32
    const int bm = blockIdx.y * 128;
    const int bn = blockIdx.x * 128;
    const int nchunks = (MODE == 6) ? 16 : (K >> 5);

    float acc[4][4][4];
    #pragma unroll
    for (int i = 0; i < 4; i++)
        #pragma unroll
        for (int j = 0; j < 4; j++)
            #pragma unroll
            for (int q = 0; q < 4; q++) acc[i][j][q] = 0.f;

    const int lr = tid >> 1;
    const int ch = (tid & 1) * 2;
    int growA = bm + lr; if (growA >= M) growA = M - 1;
    const u32 so = (u32)lr * 80u + (u32)ch * 16u;

    auto load_chunk = [&](int c, int s) {
        const __half *pA = A, *pB = B;
        int cc = c;
        if (MODE == 6 && c >= 8) { pA = A2; pB = B2; cc = c - 8; }
        const u32 base = sb + (u32)s * STAGE_BYTES;
        const size_t gbA = ((size_t)growA * K + cc * 32 + ch * 8) * 2;
        const size_t gbB = ((size_t)(bn + lr) * K + cc * 32 + ch * 8) * 2;
        cp16(base + so,                  (const char*)pA + gbA);
        cp16(base + so + 16,             (const char*)pA + gbA + 16);
        cp16(base + BUF_BYTES + so,      (const char*)pB + gbB);
        cp16(base + BUF_BYTES + so + 16, (const char*)pB + gbB + 16);
    };

    const u32 aAddr = (u32)(wm * 64 + (lane & 15)) * 80u + (u32)(lane >> 4) * 16u;
    const u32 bAddr = (u32)(wn * 32 + ((lane >> 4) << 3) + (lane & 7)) * 80u
                    + (u32)((lane >> 3) & 1) * 16u;

    load_chunk(0, 0);
    asm volatile("cp.async.commit_group;" ::: "memory");

    for (int c = 0; c < nchunks; c++) {
        const int s = c & 1;
        if (c + 1 < nchunks) {
            load_chunk(c + 1, (c + 1) & 1);
            asm volatile("cp.async.commit_group;" ::: "memory");
            asm volatile("cp.async.wait_group 1;" ::: "memory");
        } else {
            asm volatile("cp.async.wait_group 0;" ::: "memory");
        }
        __syncthreads();

        const u32 stage = sb + (u32)s * STAGE_BYTES;
        #pragma unroll
        for (int ks = 0; ks < 2; ks++) {
            u32 bfv[2][4];
            #pragma unroll
            for (int p = 0; p < 2; p++)
                ldsm4(bfv[p], stage + BUF_BYTES + bAddr + (u32)p * (16u * 80u) + (u32)ks * 32u);
            u32 af[4][4];
            #pragma unroll
            for (int mt = 0; mt < 4; mt++)
                ldsm4(af[mt], stage + aAddr + (u32)mt * (16u * 80u) + (u32)ks * 32u);
            #pragma unroll
            for (int mt = 0; mt < 4; mt++)
                #pragma unroll
                for (int nt = 0; nt < 4; nt++)
                    mma16816(acc[mt][nt], af[mt], &bfv[nt >> 1][(nt & 1) * 2]);
        }
        __syncthreads();
    }

    // ---------------- epilogue ----------------
    #pragma unroll
    for (int mt = 0; mt < 4; mt++) {
        #pragma unroll
        for (int half = 0; half < 2; half++) {
            const int r = bm + wm * 64 + mt * 16 + (lane >> 2) + half * 8;
            if (r >= M) continue;
            int g = 0;
            if (MODE == 1 || MODE == 2 || MODE == 3) g = __ldg(gidx + r);
            const size_t rowC = (size_t)r * 256;
            #pragma unroll
            for (int nt = 0; nt < 4; nt++) {
                const int c0 = bn + wn * 32 + nt * 8 + (lane & 3) * 2;
                float vx = acc[mt][nt][2 * half], vy = acc[mt][nt][2 * half + 1];
                if constexpr (MODE == 0) {
                    *(float2*)(C + rowC + c0) = make_float2(vx, vy);
                } else if constexpr (MODE == 1) {
                    const float2 ad = *(const float2*)(addmat + (size_t)g * 256 + c0);
                    const float2 bi = *(const float2*)(bias + c0);
                    vx += ad.x + bi.x; vy += ad.y + bi.y;
                    *(float2*)(C + rowC + c0) = make_float2(vx, vy);
                    *(u32*)(rout + rowC + c0) = pack2(fmaxf(vx, 0.f), fmaxf(vy, 0.f));
                } else if constexpr (MODE == 2) {
                    const size_t rowG = (size_t)g * 256;
                    float2 bs = *(float2*)(C + rowG + c0);
                    bs.x += vx; bs.y += vy;
                    *(float2*)(C + rowG + c0) = bs;
                    *(u32*)(rout + rowG + c0) = pack2(fmaxf(bs.x, 0.f), fmaxf(bs.y, 0.f));
                } else if constexpr (MODE == 3) {
                    *(float2*)(C + rowC + c0) = make_float2(vx, vy);
                    red2(agg + (size_t)g * 256 + c0, vx, vy);
                } else if constexpr (MODE == 6) {
                    const float2 bi = *(const float2*)(bias + c0);
                    *(float2*)(C + rowC + c0) =
                        make_float2(fmaxf(vx + bi.x, 0.f), fmaxf(vy + bi.y, 0.f));
                }
            }
        }
    }
}

// ---------------- fused prologue: zeros + input conversions + weight transposes ----------
#define PR_Z  (3 * NN * 64)
#define PR_FN (NN * 64)
#define PR_FE (NE * 16)
#define PR_TM (MT * 64)
#define PR_BULK (PR_Z + PR_FN + PR_FE + PR_TM)
#define PR_W  (65536 * 4 + 16384)
#define PR_TOTAL (PR_BULK + PR_W)

__global__ __launch_bounds__(256)
void prologue_k(const float* __restrict__ f_node, const float* __restrict__ f_edge,
                const float* __restrict__ tree_msg,
                const float* __restrict__ W1, const float* __restrict__ W2,
                const float* __restrict__ W3, const float* __restrict__ W4,
                const float* __restrict__ W5)
{
    int i = blockIdx.x * blockDim.x + threadIdx.x;
    if (i >= PR_TOTAL) return;
    if (i < PR_Z) {
        int j = i;
        float4* p;
        if (j < NN * 64) p = (float4*)g_aggA;
        else if (j < 2 * NN * 64) { p = (float4*)g_aggB; j -= NN * 64; }
        else { p = (float4*)g_nodesum; j -= 2 * NN * 64; }
        p[j] = make_float4(0.f, 0.f, 0.f, 0.f);
        return;
    }
    i -= PR_Z;
    if (i < PR_FN) {
        conv_store4(g_fn + (size_t)i * 4, ((const float4*)f_node)[i]);
        return;
    }
    i -= PR_FN;
    if (i < PR_FE) {
        conv_store4(g_fe + (size_t)i * 4, ((const float4*)f_edge)[i]);
        return;
    }
    i -= PR_FE;
    if (i < PR_TM) {
        conv_store4(g_tm + (size_t)i * 4, ((const float4*)tree_msg)[i]);
        return;
    }
    i -= PR_TM;
    const float* W; __half* h; int K;
    if (i < 65536)                { W = W1; h = g_B1; K = 256; }
    else if (i < 65536 + 16384)   { i -= 65536; W = W2; h = g_B2; K = 64; }
    else if (i < 2*65536 + 16384) { i -= 65536 + 16384; W = W3; h = g_B3; K = 256; }
    else if (i < 3*65536 + 16384) { i -= 2*65536 + 16384; W = W4; h = g_B4; K = 256; }
    else                          { i -= 3*65536 + 16384; W = W5; h = g_B5; K = 256; }
    int n = i / K, k = i % K;
    h[i] = __float2half_rn(W[(size_t)k * 256 + n]);
}

// ---------------- combine: m = relu(base + agg[src] - y[e^1]), 8 floats/thread --------
template<bool FINAL>
__global__ __launch_bounds__(256)
void combine_k(const float* __restrict__ base, const float* __restrict__ agg,
               const float* __restrict__ y, const int* __restrict__ esrc,
               const int* __restrict__ edst,
               __half* __restrict__ mOut, float* __restrict__ nodesum)
{
    int gid = blockIdx.x * blockDim.x + threadIdx.x;
    if (gid >= NE * 32) return;
    int e = gid >> 5;
    int c = (gid & 31) << 3;
    int s = __ldg(esrc + e);
    const float* bp = base + (size_t)e * 256 + c;
    const float* ap = agg  + (size_t)s * 256 + c;
    const float* yp = y    + (size_t)(e ^ 1) * 256 + c;
    float4 b0 = ((const float4*)bp)[0], b1 = ((const float4*)bp)[1];
    float4 a0 = ((const float4*)ap)[0], a1 = ((const float4*)ap)[1];
    float4 y0 = ((const float4*)yp)[0], y1 = ((const float4*)yp)[1];
    float m0 = fmaxf(b0.x + a0.x - y0.x, 0.f);
    float m1 = fmaxf(b0.y + a0.y - y0.y, 0.f);
    float m2 = fmaxf(b0.z + a0.z - y0.z, 0.f);
    float m3 = fmaxf(b0.w + a0.w - y0.w, 0.f);
    float m4 = fmaxf(b1.x + a1.x - y1.x, 0.f);
    float m5 = fmaxf(b1.y + a1.y - y1.y, 0.f);
    float m6 = fmaxf(b1.z + a1.z - y1.z, 0.f);
    float m7 = fmaxf(b1.w + a1.w - y1.w, 0.f);
    if (FINAL) {
        int d = __ldg(edst + e);
        float* np = nodesum + (size_t)d * 256 + c;
        red4(np,     m0, m1, m2, m3);
        red4(np + 4, m4, m5, m6, m7);
    } else {
        uint4 hv;
        hv.x = pack2(m0, m1); hv.y = pack2(m2, m3);
        hv.z = pack2(m4, m5); hv.w = pack2(m6, m7);
        *(uint4*)(mOut + (size_t)e * 256 + c) = hv;
    }
}

// convert nodesum -> fp16, 8 elems/thread
__global__ void conv_k(const float* __restrict__ x, __half* __restrict__ h, int n8)
{
    int i = blockIdx.x * blockDim.x + threadIdx.x;
    if (i >= n8) return;
    const float4* xp = (const float4*)(x + (size_t)i * 8);
    float4 v0 = xp[0], v1 = xp[1];
    uint4 hv;
    hv.x = pack2(v0.x, v0.y); hv.y = pack2(v0.z, v0.w);
    hv.z = pack2(v1.x, v1.y); hv.w = pack2(v1.z, v1.w);
    *(uint4*)(h + (size_t)i * 8) = hv;
}

// --------------------------------- launch ---------------------------------
extern "C" void kernel_launch(void* const* d_in, const int* in_sizes, int n_in,
                              void* d_out, int out_size)
{
    const float* f_node   = (const float*)d_in[0];
    const float* f_edge   = (const float*)d_in[1];
    const float* tree_msg = (const float*)d_in[2];
    const float* W1       = (const float*)d_in[3];
    const float* W2       = (const float*)d_in[4];
    const float* W3       = (const float*)d_in[5];
    const float* b1       = (const float*)d_in[6];
    const float* W4       = (const float*)d_in[7];
    const float* W5       = (const float*)d_in[8];
    const float* b2       = (const float*)d_in[9];
    const int* edge_src   = (const int*)d_in[10];
    const int* edge_dst   = (const int*)d_in[11];
    const int* tree_tgt   = (const int*)d_in[12];
    float* out = (float*)d_out;

    float *node_h, *base, *y, *aggA, *aggB, *nodesum;
    __half *fn, *fe, *tm, *am, *ns, *B1, *B2, *B3, *B4, *B5;
    cudaGetSymbolAddress((void**)&node_h,  g_node_h);
    cudaGetSymbolAddress((void**)&base,    g_base);
    cudaGetSymbolAddress((void**)&y,       g_y);
    cudaGetSymbolAddress((void**)&aggA,    g_aggA);
    cudaGetSymbolAddress((void**)&aggB,    g_aggB);
    cudaGetSymbolAddress((void**)&nodesum, g_nodesum);
    cudaGetSymbolAddress((void**)&fn, g_fn);
    cudaGetSymbolAddress((void**)&fe, g_fe);
    cudaGetSymbolAddress((void**)&tm, g_tm);
    cudaGetSymbolAddress((void**)&am, g_a);
    cudaGetSymbolAddress((void**)&ns, g_ns);
    cudaGetSymbolAddress((void**)&B1, g_B1);
    cudaGetSymbolAddress((void**)&B2, g_B2);
    cudaGetSymbolAddress((void**)&B3, g_B3);
    cudaGetSymbolAddress((void**)&B4, g_B4);
    cudaGetSymbolAddress((void**)&B5, g_B5);

    cudaFuncSetAttribute(tgemm<0>, cudaFuncAttributeMaxDynamicSharedMemorySize, SM_BYTES);
    cudaFuncSetAttribute(tgemm<1>, cudaFuncAttributeMaxDynamicSharedMemorySize, SM_BYTES);
    cudaFuncSetAttribute(tgemm<2>, cudaFuncAttributeMaxDynamicSharedMemorySize, SM_BYTES);
    cudaFuncSetAttribute(tgemm<3>, cudaFuncAttributeMaxDynamicSharedMemorySize, SM_BYTES);
    cudaFuncSetAttribute(tgemm<6>, cudaFuncAttributeMaxDynamicSharedMemorySize, SM_BYTES);

    const dim3 blk(256);
    const int combGrid = (NE * 32 + 255) / 256;
    const dim3 gN(2, (NN + 127) / 128);
    const dim3 gE(2, (NE + 127) / 128);
    const dim3 gT(2, (MT + 127) / 128);

    // ---- fused prologue: zeros + input conversions + weight transposes ----
    prologue_k<<<(PR_TOTAL + 255) / 256, blk>>>(f_node, f_edge, tree_msg, W1, W2, W3, W4, W5);

    // ---- node_h = f_node @ W1 ----
    tgemm<0><<<gN, blk, SM_BYTES>>>(fn, B1, nullptr, nullptr,
                                    node_h, NN, 256, nullptr, nullptr, nullptr, nullptr, nullptr);
    // ---- base = f_edge @ W2 + node_h[src] + b1 ; write relu fp16 -> am ----
    tgemm<1><<<gE, blk, SM_BYTES>>>(fe, B2, nullptr, nullptr,
                                    base, NE, 64, b1, node_h, edge_src, nullptr, am);
    // ---- base[tree_tgt] += tree_msg @ W3 ; patch relu rows ----
    tgemm<2><<<gT, blk, SM_BYTES>>>(tm, B3, nullptr, nullptr,
                                    base, MT, 256, nullptr, nullptr, tree_tgt, nullptr, am);

    // ---- iter 1: y1 = relu(base) @ W3 ; aggA = segsum(y1, dst) ----
    tgemm<3><<<gE, blk, SM_BYTES>>>(am, B3, nullptr, nullptr,
                                    y, NE, 256, nullptr, nullptr, edge_dst, aggA, nullptr);
    combine_k<false><<<combGrid, blk>>>(base, aggA, y, edge_src, edge_dst, am, nullptr);

    // ---- iter 2: y2 = msg2 @ W3 ; aggB = segsum(y2, dst) ----
    tgemm<3><<<gE, blk, SM_BYTES>>>(am, B3, nullptr, nullptr,
                                    y, NE, 256, nullptr, nullptr, edge_dst, aggB, nullptr);
    // ---- iter 3 fused with readout reduce ----
    combine_k<true><<<combGrid, blk>>>(base, aggB, y, edge_src, edge_dst, nullptr, nodesum);

    // ---- fused readout: out = relu(f_node @ W4 + node_sum @ W5 + b2) ----
    conv_k<<<(NN * 32 + 255) / 256, blk>>>(nodesum, ns, NN * 32);
    tgemm<6><<<gN, blk, SM_BYTES>>>(fn, B4, ns, B5,
                                    out, NN, 256, b2, nullptr, nullptr, nullptr, nullptr);
}

// round 14
// speedup vs baseline: 1.7010x; 1.0537x over previous
#include <cuda_runtime.h>
#include <cuda_fp16.h>
#include <cstdint>

#define NN 100000
#define NE 300000
#define MT 10000

typedef unsigned long long u64;
typedef unsigned int u32;

// ---------------- scratch (device globals; no allocation allowed) ----------------
__device__ float  g_node_h [(size_t)NN*256];
__device__ __half g_base   [(size_t)NE*256];   // fp16 intermediate
__device__ __half g_y      [(size_t)NE*256];   // fp16 intermediate
__device__ float  g_aggA   [(size_t)NN*256];
__device__ float  g_aggB   [(size_t)NN*256];
__device__ float  g_nodesum[(size_t)NN*256];
// single-fp16 A-side buffers
__device__ __half g_fn[(size_t)NN*256];
__device__ __half g_fe[(size_t)NE*64];
__device__ __half g_tm[(size_t)MT*256];
__device__ __half g_a [(size_t)NE*256];
__device__ __half g_ns[(size_t)NN*256];
// B matrices transposed, single fp16: B[n][k] = W[k][n]
__device__ __half g_B1[256*256];
__device__ __half g_B2[256*64];
__device__ __half g_B3[256*256];
__device__ __half g_B4[256*256];
__device__ __half g_B5[256*256];

// ---------------- helpers ----------------
__device__ __forceinline__ u32 smem_u32(const void* p) {
    u32 a; asm("{ .reg .u64 t; cvta.to.shared.u64 t, %1; cvt.u32.u64 %0, t; }" : "=r"(a) : "l"(p));
    return a;
}
__device__ __forceinline__ void cp16(u32 dst, const void* src) {
    asm volatile("cp.async.cg.shared.global [%0], [%1], 16;" :: "r"(dst), "l"(src));
}
__device__ __forceinline__ void red2(float* p, float a, float b) {
    asm volatile("red.global.add.v2.f32 [%0], {%1,%2};" :: "l"(p), "f"(a), "f"(b) : "memory");
}
__device__ __forceinline__ void red4(float* p, float a, float b, float c, float d) {
    asm volatile("red.global.add.v4.f32 [%0], {%1,%2,%3,%4};"
                 :: "l"(p), "f"(a), "f"(b), "f"(c), "f"(d) : "memory");
}
__device__ __forceinline__ void ldsm4(u32* r, u32 addr) {
    asm volatile("ldmatrix.sync.aligned.m8n8.x4.shared.b16 {%0,%1,%2,%3}, [%4];"
                 : "=r"(r[0]), "=r"(r[1]), "=r"(r[2]), "=r"(r[3]) : "r"(addr));
}
__device__ __forceinline__ void mma16816(float* d, const u32* a, const u32* b) {
    asm volatile("mma.sync.aligned.m16n8k16.row.col.f32.f16.f16.f32 "
                 "{%0,%1,%2,%3}, {%4,%5,%6,%7}, {%8,%9}, {%0,%1,%2,%3};"
                 : "+f"(d[0]), "+f"(d[1]), "+f"(d[2]), "+f"(d[3])
                 : "r"(a[0]), "r"(a[1]), "r"(a[2]), "r"(a[3]), "r"(b[0]), "r"(b[1]));
}
__device__ __forceinline__ u32 pack2(float x, float y) {
    __half2 h = __floats2half2_rn(x, y);
    return *(u32*)&h;
}
__device__ __forceinline__ float2 unpack2(u32 v) {
    __half2 h = *(__half2*)&v;
    return make_float2(__half2float(__low2half(h)), __half2float(__high2half(h)));
}
__device__ __forceinline__ void conv_store4(__half* hp, float4 v) {
    ((u32*)hp)[0] = pack2(v.x, v.y);
    ((u32*)hp)[1] = pack2(v.z, v.w);
}

// smem: 2 stages x [A | B], each buffer 128 rows x 80 bytes = 10240 B
#define BUF_BYTES 10240u
#define STAGE_BYTES (2u * BUF_BYTES)
#define SM_BYTES (2 * STAGE_BYTES)       // 40960

// ------------------- mma.sync GEMM: C[M,256] = A[M,K] @ W[K,256] -------------------
// single fp16 term, fp32 accumulate. CTA tile 128x128, grid (2, tiles_m).
// MODE 0: C(f32) = acc                                      (node_h)
// MODE 1: hC(f16) = acc + addmat[gidx[r]] + bias ; rout = relu (fp16)
// MODE 2: hC[gidx[r]](f16) += acc ; rout patched
// MODE 3: hC(f16) = acc ; red agg[gidx[r]] += acc
// MODE 6: C(f32) = relu(A@B + A2@B2 + bias)                 (fused readout; 16 chunks)
template<int MODE>
__global__ __launch_bounds__(256, 2)
void tgemm(const __half* __restrict__ A, const __half* __restrict__ B,
           const __half* __restrict__ A2, const __half* __restrict__ B2,
           float* __restrict__ C, __half* __restrict__ hC, int M, int K,
           const float* __restrict__ bias, const float* __restrict__ addmat,
           const int* __restrict__ gidx, float* __restrict__ agg,
           __half* __restrict__ rout)
{
    extern __shared__ char smem[];
    const u32 sb = smem_u32(smem);
    const int tid  = threadIdx.x;
    const int lane = tid & 31, w = tid >> 5;
    const int wm = w >> 2, wn = w & 3;
    const int bm = blockIdx.y * 128;
    const int bn = blockIdx.x * 128;
    const int nchunks = (MODE == 6) ? 16 : (K >> 5);

    float acc[4][4][4];
    #pragma unroll
    for (int i = 0; i < 4; i++)
        #pragma unroll
        for (int j = 0; j < 4; j++)
            #pragma unroll
            for (int q = 0; q < 4; q++) acc[i][j][q] = 0.f;

    const int lr = tid >> 1;
    const int ch = (tid & 1) * 2;
    int growA = bm + lr; if (growA >= M) growA = M - 1;
    const u32 so = (u32)lr * 80u + (u32)ch * 16u;

    auto load_chunk = [&](int c, int s) {
        const __half *pA = A, *pB = B;
        int cc = c;
        if (MODE == 6 && c >= 8) { pA = A2; pB = B2; cc = c - 8; }
        const u32 base = sb + (u32)s * STAGE_BYTES;
        const size_t gbA = ((size_t)growA * K + cc * 32 + ch * 8) * 2;
        const size_t gbB = ((size_t)(bn + lr) * K + cc * 32 + ch * 8) * 2;
        cp16(base + so,                  (const char*)pA + gbA);
        cp16(base + so + 16,             (const char*)pA + gbA + 16);
        cp16(base + BUF_BYTES + so,      (const char*)pB + gbB);
        cp16(base + BUF_BYTES + so + 16, (const char*)pB + gbB + 16);
    };

    const u32 aAddr = (u32)(wm * 64 + (lane & 15)) * 80u + (u32)(lane >> 4) * 16u;
    const u32 bAddr = (u32)(wn * 32 + ((lane >> 4) << 3) + (lane & 7)) * 80u
                    + (u32)((lane >> 3) & 1) * 16u;

    load_chunk(0, 0);
    asm volatile("cp.async.commit_group;" ::: "memory");

    for (int c = 0; c < nchunks; c++) {
        const int s = c & 1;
        if (c + 1 < nchunks) {
            load_chunk(c + 1, (c + 1) & 1);
            asm volatile("cp.async.commit_group;" ::: "memory");
            asm volatile("cp.async.wait_group 1;" ::: "memory");
        } else {
            asm volatile("cp.async.wait_group 0;" ::: "memory");
        }
        __syncthreads();

        const u32 stage = sb + (u32)s * STAGE_BYTES;
        #pragma unroll
        for (int ks = 0; ks < 2; ks++) {
            u32 bfv[2][4];
            #pragma unroll
            for (int p = 0; p < 2; p++)
                ldsm4(bfv[p], stage + BUF_BYTES + bAddr + (u32)p * (16u * 80u) + (u32)ks * 32u);
            u32 af[4][4];
            #pragma unroll
            for (int mt = 0; mt < 4; mt++)
                ldsm4(af[mt], stage + aAddr + (u32)mt * (16u * 80u) + (u32)ks * 32u);
            #pragma unroll
            for (int mt = 0; mt < 4; mt++)
                #pragma unroll
                for (int nt = 0; nt < 4; nt++)
                    mma16816(acc[mt][nt], af[mt], &bfv[nt >> 1][(nt & 1) * 2]);
        }
        __syncthreads();
    }

    // ---------------- epilogue ----------------
    #pragma unroll
    for (int mt = 0; mt < 4; mt++) {
        #pragma unroll
        for (int half = 0; half < 2; half++) {
            const int r = bm + wm * 64 + mt * 16 + (lane >> 2) + half * 8;
            if (r >= M) continue;
            int g = 0;
            if (MODE == 1 || MODE == 2 || MODE == 3) g = __ldg(gidx + r);
            const size_t rowC = (size_t)r * 256;
            #pragma unroll
            for (int nt = 0; nt < 4; nt++) {
                const int c0 = bn + wn * 32 + nt * 8 + (lane & 3) * 2;
                float vx = acc[mt][nt][2 * half], vy = acc[mt][nt][2 * half + 1];
                if constexpr (MODE == 0) {
                    *(float2*)(C + rowC + c0) = make_float2(vx, vy);
                } else if constexpr (MODE == 1) {
                    const float2 ad = *(const float2*)(addmat + (size_t)g * 256 + c0);
                    const float2 bi = *(const float2*)(bias + c0);
                    vx += ad.x + bi.x; vy += ad.y + bi.y;
                    *(u32*)(hC + rowC + c0)   = pack2(vx, vy);
                    *(u32*)(rout + rowC + c0) = pack2(fmaxf(vx, 0.f), fmaxf(vy, 0.f));
                } else if constexpr (MODE == 2) {
                    const size_t rowG = (size_t)g * 256;
                    float2 bs = unpack2(*(u32*)(hC + rowG + c0));
                    bs.x += vx; bs.y += vy;
                    *(u32*)(hC + rowG + c0)   = pack2(bs.x, bs.y);
                    *(u32*)(rout + rowG + c0) = pack2(fmaxf(bs.x, 0.f), fmaxf(bs.y, 0.f));
                } else if constexpr (MODE == 3) {
                    *(u32*)(hC + rowC + c0) = pack2(vx, vy);
                    red2(agg + (size_t)g * 256 + c0, vx, vy);
                } else if constexpr (MODE == 6) {
                    const float2 bi = *(const float2*)(bias + c0);
                    *(float2*)(C + rowC + c0) =
                        make_float2(fmaxf(vx + bi.x, 0.f), fmaxf(vy + bi.y, 0.f));
                }
            }
        }
    }
}

// ---------------- fused prologue: zeros + input conversions + weight transposes ----------
#define PR_Z  (3 * NN * 64)
#define PR_FN (NN * 64)
#define PR_FE (NE * 16)
#define PR_TM (MT * 64)
#define PR_BULK (PR_Z + PR_FN + PR_FE + PR_TM)
#define PR_W  (65536 * 4 + 16384)
#define PR_TOTAL (PR_BULK + PR_W)

__global__ __launch_bounds__(256)
void prologue_k(const float* __restrict__ f_node, const float* __restrict__ f_edge,
                const float* __restrict__ tree_msg,
                const float* __restrict__ W1, const float* __restrict__ W2,
                const float* __restrict__ W3, const float* __restrict__ W4,
                const float* __restrict__ W5)
{
    int i = blockIdx.x * blockDim.x + threadIdx.x;
    if (i >= PR_TOTAL) return;
    if (i < PR_Z) {
        int j = i;
        float4* p;
        if (j < NN * 64) p = (float4*)g_aggA;
        else if (j < 2 * NN * 64) { p = (float4*)g_aggB; j -= NN * 64; }
        else { p = (float4*)g_nodesum; j -= 2 * NN * 64; }
        p[j] = make_float4(0.f, 0.f, 0.f, 0.f);
        return;
    }
    i -= PR_Z;
    if (i < PR_FN) {
        conv_store4(g_fn + (size_t)i * 4, ((const float4*)f_node)[i]);
        return;
    }
    i -= PR_FN;
    if (i < PR_FE) {
        conv_store4(g_fe + (size_t)i * 4, ((const float4*)f_edge)[i]);
        return;
    }
    i -= PR_FE;
    if (i < PR_TM) {
        conv_store4(g_tm + (size_t)i * 4, ((const float4*)tree_msg)[i]);
        return;
    }
    i -= PR_TM;
    const float* W; __half* h; int K;
    if (i < 65536)                { W = W1; h = g_B1; K = 256; }
    else if (i < 65536 + 16384)   { i -= 65536; W = W2; h = g_B2; K = 64; }
    else if (i < 2*65536 + 16384) { i -= 65536 + 16384; W = W3; h = g_B3; K = 256; }
    else if (i < 3*65536 + 16384) { i -= 2*65536 + 16384; W = W4; h = g_B4; K = 256; }
    else                          { i -= 3*65536 + 16384; W = W5; h = g_B5; K = 256; }
    int n = i / K, k = i % K;
    h[i] = __float2half_rn(W[(size_t)k * 256 + n]);
}

// ---------------- combine: m = relu(base + agg[src] - y[e^1]), 8 lanes/thread --------
template<bool FINAL>
__global__ __launch_bounds__(256)
void combine_k(const __half* __restrict__ base, const float* __restrict__ agg,
               const __half* __restrict__ y, const int* __restrict__ esrc,
               const int* __restrict__ edst,
               __half* __restrict__ mOut, float* __restrict__ nodesum)
{
    int gid = blockIdx.x * blockDim.x + threadIdx.x;
    if (gid >= NE * 32) return;
    int e = gid >> 5;
    int c = (gid & 31) << 3;
    int s = __ldg(esrc + e);
    uint4 bv = *(const uint4*)(base + (size_t)e * 256 + c);
    uint4 yv = *(const uint4*)(y + (size_t)(e ^ 1) * 256 + c);
    const float4* ap = (const float4*)(agg + (size_t)s * 256 + c);
    float4 a0 = ap[0], a1 = ap[1];
    float2 b0 = unpack2(bv.x), b1 = unpack2(bv.y), b2 = unpack2(bv.z), b3 = unpack2(bv.w);
    float2 z0 = unpack2(yv.x), z1 = unpack2(yv.y), z2 = unpack2(yv.z), z3 = unpack2(yv.w);
    float m0 = fmaxf(b0.x + a0.x - z0.x, 0.f);
    float m1 = fmaxf(b0.y + a0.y - z0.y, 0.f);
    float m2 = fmaxf(b1.x + a0.z - z1.x, 0.f);
    float m3 = fmaxf(b1.y + a0.w - z1.y, 0.f);
    float m4 = fmaxf(b2.x + a1.x - z2.x, 0.f);
    float m5 = fmaxf(b2.y + a1.y - z2.y, 0.f);
    float m6 = fmaxf(b3.x + a1.z - z3.x, 0.f);
    float m7 = fmaxf(b3.y + a1.w - z3.y, 0.f);
    if (FINAL) {
        int d = __ldg(edst + e);
        float* np = nodesum + (size_t)d * 256 + c;
        red4(np,     m0, m1, m2, m3);
        red4(np + 4, m4, m5, m6, m7);
    } else {
        uint4 hv;
        hv.x = pack2(m0, m1); hv.y = pack2(m2, m3);
        hv.z = pack2(m4, m5); hv.w = pack2(m6, m7);
        *(uint4*)(mOut + (size_t)e * 256 + c) = hv;
    }
}

// convert nodesum -> fp16, 8 elems/thread
__global__ void conv_k(const float* __restrict__ x, __half* __restrict__ h, int n8)
{
    int i = blockIdx.x * blockDim.x + threadIdx.x;
    if (i >= n8) return;
    const float4* xp = (const float4*)(x + (size_t)i * 8);
    float4 v0 = xp[0], v1 = xp[1];
    uint4 hv;
    hv.x = pack2(v0.x, v0.y); hv.y = pack2(v0.z, v0.w);
    hv.z = pack2(v1.x, v1.y); hv.w = pack2(v1.z, v1.w);
    *(uint4*)(h + (size_t)i * 8) = hv;
}

// --------------------------------- launch ---------------------------------
extern "C" void kernel_launch(void* const* d_in, const int* in_sizes, int n_in,
                              void* d_out, int out_size)
{
    const float* f_node   = (const float*)d_in[0];
    const float* f_edge   = (const float*)d_in[1];
    const float* tree_msg = (const float*)d_in[2];
    const float* W1       = (const float*)d_in[3];
    const float* W2       = (const float*)d_in[4];
    const float* W3       = (const float*)d_in[5];
    const float* b1       = (const float*)d_in[6];
    const float* W4       = (const float*)d_in[7];
    const float* W5       = (const float*)d_in[8];
    const float* b2       = (const float*)d_in[9];
    const int* edge_src   = (const int*)d_in[10];
    const int* edge_dst   = (const int*)d_in[11];
    const int* tree_tgt   = (const int*)d_in[12];
    float* out = (float*)d_out;

    float *node_h, *aggA, *aggB, *nodesum;
    __half *base, *y, *fn, *fe, *tm, *am, *ns, *B1, *B2, *B3, *B4, *B5;
    cudaGetSymbolAddress((void**)&node_h,  g_node_h);
    cudaGetSymbolAddress((void**)&base,    g_base);
    cudaGetSymbolAddress((void**)&y,       g_y);
    cudaGetSymbolAddress((void**)&aggA,    g_aggA);
    cudaGetSymbolAddress((void**)&aggB,    g_aggB);
    cudaGetSymbolAddress((void**)&nodesum, g_nodesum);
    cudaGetSymbolAddress((void**)&fn, g_fn);
    cudaGetSymbolAddress((void**)&fe, g_fe);
    cudaGetSymbolAddress((void**)&tm, g_tm);
    cudaGetSymbolAddress((void**)&am, g_a);
    cudaGetSymbolAddress((void**)&ns, g_ns);
    cudaGetSymbolAddress((void**)&B1, g_B1);
    cudaGetSymbolAddress((void**)&B2, g_B2);
    cudaGetSymbolAddress((void**)&B3, g_B3);
    cudaGetSymbolAddress((void**)&B4, g_B4);
    cudaGetSymbolAddress((void**)&B5, g_B5);

    cudaFuncSetAttribute(tgemm<0>, cudaFuncAttributeMaxDynamicSharedMemorySize, SM_BYTES);
    cudaFuncSetAttribute(tgemm<1>, cudaFuncAttributeMaxDynamicSharedMemorySize, SM_BYTES);
    cudaFuncSetAttribute(tgemm<2>, cudaFuncAttributeMaxDynamicSharedMemorySize, SM_BYTES);
    cudaFuncSetAttribute(tgemm<3>, cudaFuncAttributeMaxDynamicSharedMemorySize, SM_BYTES);
    cudaFuncSetAttribute(tgemm<6>, cudaFuncAttributeMaxDynamicSharedMemorySize, SM_BYTES);

    const dim3 blk(256);
    const int combGrid = (NE * 32 + 255) / 256;
    const dim3 gN(2, (NN + 127) / 128);
    const dim3 gE(2, (NE + 127) / 128);
    const dim3 gT(2, (MT + 127) / 128);

    // ---- fused prologue ----
    prologue_k<<<(PR_TOTAL + 255) / 256, blk>>>(f_node, f_edge, tree_msg, W1, W2, W3, W4, W5);

    // ---- node_h = f_node @ W1 ----
    tgemm<0><<<gN, blk, SM_BYTES>>>(fn, B1, nullptr, nullptr,
                                    node_h, nullptr, NN, 256, nullptr, nullptr, nullptr, nullptr, nullptr);
    // ---- base(f16) = f_edge @ W2 + node_h[src] + b1 ; am = relu ----
    tgemm<1><<<gE, blk, SM_BYTES>>>(fe, B2, nullptr, nullptr,
                                    nullptr, base, NE, 64, b1, node_h, edge_src, nullptr, am);
    // ---- base[tree_tgt] += tree_msg @ W3 ; patch am ----
    tgemm<2><<<gT, blk, SM_BYTES>>>(tm, B3, nullptr, nullptr,
                                    nullptr, base, MT, 256, nullptr, nullptr, tree_tgt, nullptr, am);

    // ---- iter 1: y1(f16) = relu(base) @ W3 ; aggA = segsum(y1, dst) ----
    tgemm<3><<<gE, blk, SM_BYTES>>>(am, B3, nullptr, nullptr,
                                    nullptr, y, NE, 256, nullptr, nullptr, edge_dst, aggA, nullptr);
    combine_k<false><<<combGrid, blk>>>(base, aggA, y, edge_src, edge_dst, am, nullptr);

    // ---- iter 2: y2(f16) = msg2 @ W3 ; aggB = segsum(y2, dst) ----
    tgemm<3><<<gE, blk, SM_BYTES>>>(am, B3, nullptr, nullptr,
                                    nullptr, y, NE, 256, nullptr, nullptr, edge_dst, aggB, nullptr);
    // ---- iter 3 fused with readout reduce ----
    combine_k<true><<<combGrid, blk>>>(base, aggB, y, edge_src, edge_dst, nullptr, nodesum);

    // ---- fused readout: out = relu(f_node @ W4 + node_sum @ W5 + b2) ----
    conv_k<<<(NN * 32 + 255) / 256, blk>>>(nodesum, ns, NN * 32);
    tgemm<6><<<gN, blk, SM_BYTES>>>(fn, B4, ns, B5,
                                    out, nullptr, NN, 256, b2, nullptr, nullptr, nullptr, nullptr);
}